// round 3
// baseline (speedup 1.0000x reference)
#include <cuda_runtime.h>
#include <cstdint>

// ---------------------------------------------------------------------------
// SGConv on GB300: h_{k+1} = D^-1/2 (A + I) D^-1/2 h_k  (3 hops), then h W^T + b
// N=100000, E=800000, D=128.
// Warp-per-edge scatter with red.global.add.v4.f32 (no-return 16B vector
// reductions). edge_index is int32 (JAX x64-disabled coerces the reference's
// int64 request to int32). All scratch in __device__ globals; kernel_launch
// contains ONLY kernel launches.
// ---------------------------------------------------------------------------

#define NN   100000
#define EE   800000
#define DIM  128
#define D4   32          // DIM / 4 float4s per row

__device__ float  g_deg [NN];
__device__ float  g_dinv[NN];
__device__ float4 g_h1  [NN * D4];   // 51.2 MB
__device__ float4 g_h2  [NN * D4];   // 51.2 MB

__device__ __forceinline__ float4* buf(int sel) {
    return (sel == 0) ? g_h1 : g_h2;
}

// ---------------------------------------------------------------------------
__global__ void init_deg_kernel() {
    int i = blockIdx.x * blockDim.x + threadIdx.x;
    if (i < NN) g_deg[i] = 1.0f;          // self-loop contributes 1
}

__global__ void count_deg_kernel(const int* __restrict__ ei) {
    int e = blockIdx.x * blockDim.x + threadIdx.x;
    if (e < EE) {
        int dst = ei[EE + e];
        atomicAdd(&g_deg[dst], 1.0f);
    }
}

__global__ void dinv_kernel() {
    int i = blockIdx.x * blockDim.x + threadIdx.x;
    if (i < NN) g_dinv[i] = rsqrtf(g_deg[i]);   // deg >= 1 always
}

// hout[i] = hin[i] * dinv[node]^2  (self-loop term; also initializes hout).
// hinSel: -1 -> external x pointer; 0/1 -> g_h1/g_h2.
__global__ void self_init_kernel(const float4* __restrict__ x,
                                 int hinSel, int houtSel) {
    const float4* hin  = (hinSel < 0) ? x : buf(hinSel);
    float4*       hout = buf(houtSel);
    int i = blockIdx.x * blockDim.x + threadIdx.x;   // over NN*D4
    if (i < NN * D4) {
        int node = i >> 5;
        float s = g_dinv[node];
        s = s * s;
        float4 v = hin[i];
        v.x *= s; v.y *= s; v.z *= s; v.w *= s;
        hout[i] = v;
    }
}

// One warp per edge. Lane l handles float4 #l of the 128-float row.
__global__ void scatter_kernel(const int* __restrict__ ei,
                               const float4* __restrict__ x,
                               int hinSel, int houtSel) {
    const float4* hin  = (hinSel < 0) ? x : buf(hinSel);
    float4*       hout = buf(houtSel);
    int t    = blockIdx.x * blockDim.x + threadIdx.x;
    int e    = t >> 5;
    int lane = t & 31;
    if (e < EE) {
        int src = ei[e];              // uniform across warp -> 1 request
        int dst = ei[EE + e];
        float norm = g_dinv[src] * g_dinv[dst];
        float4 v = hin[src * D4 + lane];
        v.x *= norm; v.y *= norm; v.z *= norm; v.w *= norm;
        float* addr = (float*)(hout + dst * D4 + lane);
        asm volatile("red.global.add.v4.f32 [%0], {%1, %2, %3, %4};"
                     :: "l"(addr), "f"(v.x), "f"(v.y), "f"(v.z), "f"(v.w)
                     : "memory");
    }
}

// y[node][j] = b[j] + sum_k h[node][k] * W[j][k].  One block per node;
// final hop result lives in g_h1.
__global__ void linear_kernel(const float*  __restrict__ W,
                              const float*  __restrict__ b,
                              float* __restrict__ out) {
    __shared__ float4 sh[D4];
    int node = blockIdx.x;
    int j    = threadIdx.x;          // 128 threads, one output column each
    if (j < D4) sh[j] = g_h1[node * D4 + j];
    __syncthreads();

    const float4* Wr = (const float4*)(W + j * DIM);   // W row j (K-contig)
    float acc = b[j];
#pragma unroll
    for (int k = 0; k < D4; k++) {
        float4 w  = Wr[k];
        float4 hv = sh[k];
        acc += w.x * hv.x + w.y * hv.y + w.z * hv.z + w.w * hv.w;
    }
    out[node * DIM + j] = acc;
}

// ---------------------------------------------------------------------------
extern "C" void kernel_launch(void* const* d_in, const int* in_sizes, int n_in,
                              void* d_out, int out_size) {
    const float* x  = (const float*)d_in[0];
    const int*   ei = (const int*)d_in[1];
    const float* W  = (const float*)d_in[2];
    const float* b  = (const float*)d_in[3];
    float*       out = (float*)d_out;
    const float4* x4 = (const float4*)x;

    const int TB = 256;
    const int rowElems   = NN * D4;
    const int selfBlocks = (rowElems + TB - 1) / TB;
    const long long scatterThreads = (long long)EE * 32;
    const int scatBlocks = (int)((scatterThreads + TB - 1) / TB);

    // --- degree / normalization ---
    init_deg_kernel <<<(NN + TB - 1) / TB, TB>>>();
    count_deg_kernel<<<(EE + TB - 1) / TB, TB>>>(ei);
    dinv_kernel     <<<(NN + TB - 1) / TB, TB>>>();

    // --- hop 1: x -> g_h1 ---
    self_init_kernel<<<selfBlocks, TB>>>(x4, -1, 0);
    scatter_kernel  <<<scatBlocks, TB>>>(ei, x4, -1, 0);
    // --- hop 2: g_h1 -> g_h2 ---
    self_init_kernel<<<selfBlocks, TB>>>(x4, 0, 1);
    scatter_kernel  <<<scatBlocks, TB>>>(ei, x4, 0, 1);
    // --- hop 3: g_h2 -> g_h1 ---
    self_init_kernel<<<selfBlocks, TB>>>(x4, 1, 0);
    scatter_kernel  <<<scatBlocks, TB>>>(ei, x4, 1, 0);

    // --- final linear ---
    linear_kernel<<<NN, DIM>>>(W, b, out);
}

// round 4
// speedup vs baseline: 1.1061x; 1.1061x over previous
#include <cuda_runtime.h>
#include <cstdint>

// ---------------------------------------------------------------------------
// SGConv on GB300 — pull formulation (no atomics in the hop loop).
// h_{k+1}[n] = dinv[n]^2 * h_k[n] + sum_{e: dst(e)=n} dinv[src]*dinv[n]*h_k[src]
// 3 hops, then y = h W^T + b.   N=100000, E=800000, D=128.
//
// Per launch: build capped in-adjacency slots (int atomics, ~10us), derive
// degrees from the fill cursors, then 3 pull hops (warp-per-node register
// accumulation, coalesced 512B gathers from the L2-resident feature buffer),
// then the 128x128 linear. kernel_launch contains ONLY kernel launches.
// ---------------------------------------------------------------------------

#define NN   100000
#define EE   800000
#define DIM  128
#define D4   32          // DIM/4 float4s per row
#define CAP  96          // in-edge slot capacity per node (max degree ~30)

__device__ int    g_cnt [NN];         // in-degree (excl. self), fill cursor
__device__ int    g_col [NN * CAP];   // in-edge source ids (38.4 MB)
__device__ float  g_dinv[NN];
__device__ float4 g_h1  [NN * D4];    // 51.2 MB
__device__ float4 g_h2  [NN * D4];    // 51.2 MB

__device__ __forceinline__ float4* buf(int sel) {
    return (sel == 0) ? g_h1 : g_h2;
}

// ---------------------------------------------------------------------------
__global__ void zero_cnt_kernel() {
    int i = blockIdx.x * blockDim.x + threadIdx.x;
    if (i < NN) g_cnt[i] = 0;
}

__global__ void fill_kernel(const int* __restrict__ ei) {
    int e = blockIdx.x * blockDim.x + threadIdx.x;
    if (e < EE) {
        int src = ei[e];
        int dst = ei[EE + e];
        int pos = atomicAdd(&g_cnt[dst], 1);
        if (pos < CAP) g_col[dst * CAP + pos] = src;
    }
}

__global__ void dinv_kernel() {
    int i = blockIdx.x * blockDim.x + threadIdx.x;
    if (i < NN) g_dinv[i] = rsqrtf((float)(g_cnt[i] + 1));  // +1 self-loop
}

// One warp per node. Lane l owns float4 #l of the 128-float row.
// Lanes cooperatively read <=32 in-edge ids + dinv[src] (coalesced), then
// shfl-broadcast each (src, norm) and gather h[src] rows. No atomics.
__global__ void pull_kernel(const float4* __restrict__ x,
                            int hinSel, int houtSel) {
    const float4* __restrict__ hin  = (hinSel < 0) ? x : buf(hinSel);
    float4*       __restrict__ hout = buf(houtSel);
    int t    = blockIdx.x * blockDim.x + threadIdx.x;
    int n    = t >> 5;
    int lane = t & 31;
    if (n >= NN) return;

    int   cnt = g_cnt[n];
    if (cnt > CAP) cnt = CAP;
    float dn  = g_dinv[n];

    // self-loop term
    float4 acc = hin[n * D4 + lane];
    float  ss  = dn * dn;
    acc.x *= ss; acc.y *= ss; acc.z *= ss; acc.w *= ss;

    int base = n * CAP;
    for (int c0 = 0; c0 < cnt; c0 += 32) {
        int m = cnt - c0; if (m > 32) m = 32;
        int   myCol = 0;
        float myNrm = 0.0f;
        if (lane < m) {
            myCol = g_col[base + c0 + lane];
            myNrm = g_dinv[myCol];
        }
        #pragma unroll 4
        for (int i = 0; i < m; i++) {
            int   s  = __shfl_sync(0xffffffffu, myCol, i);
            float nr = __shfl_sync(0xffffffffu, myNrm, i) * dn;
            float4 v = hin[s * D4 + lane];
            acc.x += v.x * nr; acc.y += v.y * nr;
            acc.z += v.z * nr; acc.w += v.w * nr;
        }
    }
    hout[n * D4 + lane] = acc;
}

// y[node][j] = b[j] + sum_k h[node][k] * W[j][k]. One block per node;
// final hop result lives in g_h1.
__global__ void linear_kernel(const float* __restrict__ W,
                              const float* __restrict__ b,
                              float* __restrict__ out) {
    __shared__ float4 sh[D4];
    int node = blockIdx.x;
    int j    = threadIdx.x;           // 128 threads, one output column each
    if (j < D4) sh[j] = g_h1[node * D4 + j];
    __syncthreads();

    const float4* Wr = (const float4*)(W + j * DIM);
    float acc = b[j];
#pragma unroll
    for (int k = 0; k < D4; k++) {
        float4 w  = Wr[k];
        float4 hv = sh[k];
        acc += w.x * hv.x + w.y * hv.y + w.z * hv.z + w.w * hv.w;
    }
    out[node * DIM + j] = acc;
}

// ---------------------------------------------------------------------------
extern "C" void kernel_launch(void* const* d_in, const int* in_sizes, int n_in,
                              void* d_out, int out_size) {
    const float* x   = (const float*)d_in[0];
    const int*   ei  = (const int*)d_in[1];
    const float* W   = (const float*)d_in[2];
    const float* b   = (const float*)d_in[3];
    float*       out = (float*)d_out;
    const float4* x4 = (const float4*)x;

    const int TB = 256;
    const int nodeBlocks = (NN + TB - 1) / TB;
    const int edgeBlocks = (EE + TB - 1) / TB;
    const int pullBlocks = (NN * 32 + TB - 1) / TB;   // warp per node

    // adjacency + normalization (rebuilt every launch; deterministic)
    zero_cnt_kernel<<<nodeBlocks, TB>>>();
    fill_kernel    <<<edgeBlocks, TB>>>(ei);
    dinv_kernel    <<<nodeBlocks, TB>>>();

    // 3 pull hops: x -> h1 -> h2 -> h1
    pull_kernel<<<pullBlocks, TB>>>(x4, -1, 0);
    pull_kernel<<<pullBlocks, TB>>>(x4,  0, 1);
    pull_kernel<<<pullBlocks, TB>>>(x4,  1, 0);

    // final linear
    linear_kernel<<<NN, DIM>>>(W, b, out);
}

// round 5
// speedup vs baseline: 6.3163x; 5.7105x over previous
#include <cuda_runtime.h>
#include <cstdint>

// ---------------------------------------------------------------------------
// SGConv on GB300 — pull hops + register-blocked tiled GEMM epilogue.
// N=100000, E=800000, D=128, 3 hops.
// ---------------------------------------------------------------------------

#define NN   100000
#define EE   800000
#define DIM  128
#define D4   32          // DIM/4 float4s per row
#define CAP  96          // in-edge slot capacity per node (max degree ~30)

#define BM   128         // GEMM node-tile
#define BK   32          // GEMM k-chunk
#define LDT  132         // smem row stride (floats), 16B-aligned, padded

__device__ int    g_cnt [NN];
__device__ int    g_col [NN * CAP];   // 38.4 MB
__device__ float  g_dinv[NN];
__device__ float4 g_h1  [NN * D4];    // 51.2 MB
__device__ float4 g_h2  [NN * D4];    // 51.2 MB

__device__ __forceinline__ float4* buf(int sel) {
    return (sel == 0) ? g_h1 : g_h2;
}

// ---------------------------------------------------------------------------
__global__ void zero_cnt_kernel() {
    int i = blockIdx.x * blockDim.x + threadIdx.x;
    if (i < NN) g_cnt[i] = 0;
}

__global__ void fill_kernel(const int* __restrict__ ei) {
    int e = blockIdx.x * blockDim.x + threadIdx.x;
    if (e < EE) {
        int src = ei[e];
        int dst = ei[EE + e];
        int pos = atomicAdd(&g_cnt[dst], 1);
        if (pos < CAP) g_col[dst * CAP + pos] = src;
    }
}

__global__ void dinv_kernel() {
    int i = blockIdx.x * blockDim.x + threadIdx.x;
    if (i < NN) g_dinv[i] = rsqrtf((float)(g_cnt[i] + 1));  // +1 self-loop
}

// One warp per node; lane l owns float4 #l of the row. No atomics.
__global__ void pull_kernel(const float4* __restrict__ x,
                            int hinSel, int houtSel) {
    const float4* __restrict__ hin  = (hinSel < 0) ? x : buf(hinSel);
    float4*       __restrict__ hout = buf(houtSel);
    int t    = blockIdx.x * blockDim.x + threadIdx.x;
    int n    = t >> 5;
    int lane = t & 31;
    if (n >= NN) return;

    int   cnt = g_cnt[n];
    if (cnt > CAP) cnt = CAP;
    float dn  = g_dinv[n];

    float4 acc = hin[n * D4 + lane];
    float  ss  = dn * dn;
    acc.x *= ss; acc.y *= ss; acc.z *= ss; acc.w *= ss;

    int base = n * CAP;
    for (int c0 = 0; c0 < cnt; c0 += 32) {
        int m = cnt - c0; if (m > 32) m = 32;
        int   myCol = 0;
        float myNrm = 0.0f;
        if (lane < m) {
            myCol = g_col[base + c0 + lane];
            myNrm = g_dinv[myCol];
        }
        #pragma unroll 4
        for (int i = 0; i < m; i++) {
            int   s  = __shfl_sync(0xffffffffu, myCol, i);
            float nr = __shfl_sync(0xffffffffu, myNrm, i) * dn;
            float4 v = hin[s * D4 + lane];
            acc.x += v.x * nr; acc.y += v.y * nr;
            acc.z += v.z * nr; acc.w += v.w * nr;
        }
    }
    hout[n * D4 + lane] = acc;
}

// ---------------------------------------------------------------------------
// Tiled GEMM: out[BM x 128] = H[BM x 128] * W^T + b, H = g_h1.
// 256 threads = 16x16; each thread owns an 8x8 output tile.
// Smem tiles stored k-major (Ht[k][row], Wt[k][col]) -> conflict-free LDS.128.
__global__ __launch_bounds__(256) void linear_gemm_kernel(
        const float* __restrict__ W,
        const float* __restrict__ bias,
        float* __restrict__ out) {
    __shared__ float Ht[BK][LDT];    // [k][node-in-tile]
    __shared__ float Wt[BK][LDT];    // [k][out-col]

    int tid = threadIdx.x;
    int tx  = tid & 15;              // out-col group (8 cols)
    int ty  = tid >> 4;              // node group   (8 rows)
    int rowBase = blockIdx.x * BM;

    const float* H = (const float*)g_h1;

    float acc[8][8];
#pragma unroll
    for (int i = 0; i < 8; i++)
#pragma unroll
        for (int j = 0; j < 8; j++) acc[i][j] = 0.0f;

    for (int kc = 0; kc < DIM; kc += BK) {
        // Stage H chunk (transpose to k-major). 128 rows x 8 float4s.
#pragma unroll
        for (int it = 0; it < 4; it++) {
            int idx = tid + it * 256;        // 0..1023
            int r   = idx >> 3;              // node-in-tile
            int c4  = idx & 7;               // float4 within chunk
            int node = rowBase + r;
            float4 v = make_float4(0.f, 0.f, 0.f, 0.f);
            if (node < NN)
                v = *(const float4*)(H + (size_t)node * DIM + kc + c4 * 4);
            Ht[c4 * 4 + 0][r] = v.x;
            Ht[c4 * 4 + 1][r] = v.y;
            Ht[c4 * 4 + 2][r] = v.z;
            Ht[c4 * 4 + 3][r] = v.w;
        }
        // Stage W chunk (transpose to k-major). 128 cols x 8 float4s.
#pragma unroll
        for (int it = 0; it < 4; it++) {
            int idx = tid + it * 256;
            int j   = idx >> 3;
            int c4  = idx & 7;
            float4 v = *(const float4*)(W + (size_t)j * DIM + kc + c4 * 4);
            Wt[c4 * 4 + 0][j] = v.x;
            Wt[c4 * 4 + 1][j] = v.y;
            Wt[c4 * 4 + 2][j] = v.z;
            Wt[c4 * 4 + 3][j] = v.w;
        }
        __syncthreads();

#pragma unroll
        for (int k = 0; k < BK; k++) {
            float4 a0 = *(const float4*)&Ht[k][ty * 8];
            float4 a1 = *(const float4*)&Ht[k][ty * 8 + 4];
            float4 b0 = *(const float4*)&Wt[k][tx * 8];
            float4 b1 = *(const float4*)&Wt[k][tx * 8 + 4];
            float a[8] = {a0.x, a0.y, a0.z, a0.w, a1.x, a1.y, a1.z, a1.w};
            float b[8] = {b0.x, b0.y, b0.z, b0.w, b1.x, b1.y, b1.z, b1.w};
#pragma unroll
            for (int i = 0; i < 8; i++)
#pragma unroll
                for (int j = 0; j < 8; j++)
                    acc[i][j] += a[i] * b[j];
        }
        __syncthreads();
    }

    // Epilogue: add bias, store two float4s per row.
    float bj[8];
#pragma unroll
    for (int j = 0; j < 8; j++) bj[j] = bias[tx * 8 + j];

#pragma unroll
    for (int i = 0; i < 8; i++) {
        int node = rowBase + ty * 8 + i;
        if (node < NN) {
            float4 o0 = make_float4(acc[i][0] + bj[0], acc[i][1] + bj[1],
                                    acc[i][2] + bj[2], acc[i][3] + bj[3]);
            float4 o1 = make_float4(acc[i][4] + bj[4], acc[i][5] + bj[5],
                                    acc[i][6] + bj[6], acc[i][7] + bj[7]);
            float* dst = out + (size_t)node * DIM + tx * 8;
            *(float4*)(dst)     = o0;
            *(float4*)(dst + 4) = o1;
        }
    }
}

// ---------------------------------------------------------------------------
extern "C" void kernel_launch(void* const* d_in, const int* in_sizes, int n_in,
                              void* d_out, int out_size) {
    const float* x   = (const float*)d_in[0];
    const int*   ei  = (const int*)d_in[1];
    const float* W   = (const float*)d_in[2];
    const float* b   = (const float*)d_in[3];
    float*       out = (float*)d_out;
    const float4* x4 = (const float4*)x;

    const int TB = 256;
    const int nodeBlocks = (NN + TB - 1) / TB;
    const int edgeBlocks = (EE + TB - 1) / TB;
    const int pullBlocks = (NN * 32 + TB - 1) / TB;   // warp per node
    const int gemmBlocks = (NN + BM - 1) / BM;

    zero_cnt_kernel<<<nodeBlocks, TB>>>();
    fill_kernel    <<<edgeBlocks, TB>>>(ei);
    dinv_kernel    <<<nodeBlocks, TB>>>();

    pull_kernel<<<pullBlocks, TB>>>(x4, -1, 0);
    pull_kernel<<<pullBlocks, TB>>>(x4,  0, 1);
    pull_kernel<<<pullBlocks, TB>>>(x4,  1, 0);

    linear_gemm_kernel<<<gemmBlocks, 256>>>(W, b, out);
}